// round 1
// baseline (speedup 1.0000x reference)
#include <cuda_runtime.h>
#include <cuda_bf16.h>

#define Hn   128
#define Bn   64
#define Tn   128
#define Ln   2
#define LATn 512
#define UNF  6
#define EPSV 1e-8f

// ---------------- static device scratch (no allocations allowed) ----------------
// transformed params: [layer][{rec_a, rec_b, rec_hwe, sen_a, sen_b, sen_hwe}][H*H]
__device__ float g_par[Ln][6][Hn * Hn];
__device__ float g_ns[Tn * Bn * Hn];   // sensory numerator  [T,B,H]
__device__ float g_ds[Tn * Bn * Hn];   // sensory denominator [T,B,H]
__device__ float g_h0[Tn * Bn * Hn];   // layer-0 hidden seq [T,B,H]
__device__ float g_h1[Bn * Tn * Hn];   // layer-1 hidden, flat [B, T*H] for the heads

__device__ __forceinline__ float tanh_fast(float x) {
    float y;
    asm("tanh.approx.f32 %0, %1;" : "=f"(y) : "f"(x));
    return y;
}

// ---------------- param transform ----------------
// rec_a = 0.5*sigma ; rec_b = -0.5*mu*sigma ; rec_hwe = 0.5*w*erev  (same for sensory)
__global__ void prep_kernel(const float* __restrict__ sg,  const float* __restrict__ mu,
                            const float* __restrict__ w,   const float* __restrict__ er,
                            const float* __restrict__ ssg, const float* __restrict__ smu,
                            const float* __restrict__ sw,  const float* __restrict__ ser)
{
    int idx = blockIdx.x * blockDim.x + threadIdx.x;
    if (idx >= Ln * Hn * Hn) return;
    int l = idx >> 14;
    int k = idx & (Hn * Hn - 1);
    float a = sg[idx], m = mu[idx];
    g_par[l][0][k] = 0.5f * a;
    g_par[l][1][k] = -0.5f * m * a;
    g_par[l][2][k] = 0.5f * w[idx] * er[idx];
    float sa = ssg[idx], sm2 = smu[idx];
    g_par[l][3][k] = 0.5f * sa;
    g_par[l][4][k] = -0.5f * sm2 * sa;
    g_par[l][5][k] = 0.5f * sw[idx] * ser[idx];
}

// ---------------- sensory precompute ----------------
// grid (T/4, B), 256 threads. Each block: 4 timesteps of one batch, full D x H reduction.
// Params streamed from L2 (reused x4 timesteps per load).
__global__ void __launch_bounds__(256) sensory_kernel(int layer, const float* __restrict__ x)
{
    __shared__ float su[4][Hn];
    __shared__ float pn[4][8][Hn];
    __shared__ float pd[4][8][Hn];

    const int tg   = blockIdx.x;       // timestep group
    const int b    = blockIdx.y;
    const int t0   = tg * 4;
    const int tid  = threadIdx.x;
    const int w    = tid >> 5;         // i-chunk 0..7 (16 rows each)
    const int lane = tid & 31;         // j-vec (4 cols each)

    const float* ub; int ust, usb;
    if (layer == 0) { ub = x;    ust = Hn;      usb = Tn * Hn; }  // x[b][t][i]
    else            { ub = g_h0; ust = Bn * Hn; usb = Hn;      }  // h0[t][b][i]

    for (int k = tid; k < 4 * Hn; k += 256) {
        int tt = k >> 7, i = k & 127;
        su[tt][i] = ub[(size_t)b * usb + (size_t)(t0 + tt) * ust + i];
    }
    __syncthreads();

    const float4* pa = (const float4*)g_par[layer][3];
    const float4* pb = (const float4*)g_par[layer][4];
    const float4* pw = (const float4*)g_par[layer][5];

    float4 an[4], ad[4];
#pragma unroll
    for (int tt = 0; tt < 4; tt++) { an[tt] = make_float4(0,0,0,0); ad[tt] = make_float4(0,0,0,0); }

#pragma unroll 2
    for (int ii = 0; ii < 16; ii++) {
        int i = w * 16 + ii;
        float4 A  = pa[i * 32 + lane];
        float4 Bv = pb[i * 32 + lane];
        float4 W  = pw[i * 32 + lane];
#pragma unroll
        for (int tt = 0; tt < 4; tt++) {
            float vi = su[tt][i];
            float th, tv;
            th = tanh_fast(fmaf(vi, A.x, Bv.x)); tv = fmaf(W.x, th, W.x); an[tt].x += tv; ad[tt].x += fabsf(tv);
            th = tanh_fast(fmaf(vi, A.y, Bv.y)); tv = fmaf(W.y, th, W.y); an[tt].y += tv; ad[tt].y += fabsf(tv);
            th = tanh_fast(fmaf(vi, A.z, Bv.z)); tv = fmaf(W.z, th, W.z); an[tt].z += tv; ad[tt].z += fabsf(tv);
            th = tanh_fast(fmaf(vi, A.w, Bv.w)); tv = fmaf(W.w, th, W.w); an[tt].w += tv; ad[tt].w += fabsf(tv);
        }
    }
#pragma unroll
    for (int tt = 0; tt < 4; tt++) {
        ((float4*)&pn[tt][w][0])[lane] = an[tt];
        ((float4*)&pd[tt][w][0])[lane] = ad[tt];
    }
    __syncthreads();

    for (int p = tid; p < 512; p += 256) {
        int tt = p >> 7, j = p & 127;
        float n = 0.f, d = 0.f;
#pragma unroll
        for (int c = 0; c < 8; c++) { n += pn[tt][c][j]; d += pd[tt][c][j]; }
        int off = ((t0 + tt) * Bn + b) * Hn + j;
        g_ns[off] = n;
        g_ds[off] = d;
    }
}

// ---------------- LTC scan (persistent per-batch block) ----------------
// 64 blocks (one batch each), 512 threads, all 3 recurrent param matrices in smem.
// Per unfold: warp w handles i in [8w, 8w+8), lane handles 4 consecutive j.
#define SCAN_SMEM_FLOATS (3 * Hn * Hn + Hn + 2 * 16 * Hn)
#define SCAN_SMEM_BYTES  (SCAN_SMEM_FLOATS * 4)

__global__ void __launch_bounds__(512) scan_kernel(
    int layer, const float* __restrict__ gleak, const float* __restrict__ vleak,
    const float* __restrict__ cm)
{
    extern __shared__ float sm[];
    float* s_a  = sm;
    float* s_b  = sm + Hn * Hn;
    float* s_w  = sm + 2 * Hn * Hn;
    float* s_v  = sm + 3 * Hn * Hn;        // [H] state
    float* s_pn = s_v + Hn;                // [16][H] partial num
    float* s_pd = s_pn + 16 * Hn;          // [16][H] partial den

    const int b    = blockIdx.x;
    const int tid  = threadIdx.x;
    const int w    = tid >> 5;    // 0..15 i-chunk
    const int lane = tid & 31;    // j-vec

    {   // stage params (amortized over 128 timesteps)
        const float4* pa = (const float4*)g_par[layer][0];
        const float4* pb = (const float4*)g_par[layer][1];
        const float4* pw = (const float4*)g_par[layer][2];
        float4* sa = (float4*)s_a; float4* sb = (float4*)s_b; float4* sw4 = (float4*)s_w;
        for (int k = tid; k < (Hn * Hn) / 4; k += 512) { sa[k] = pa[k]; sb[k] = pb[k]; sw4[k] = pw[k]; }
    }

    float cmt = 0.f, glr = 0.f, glvl = 0.f;
    if (tid < Hn) {
        float g  = gleak[layer * Hn + tid];
        float vv = vleak[layer * Hn + tid];
        float c  = cm[layer * Hn + tid];
        cmt = c * (float)UNF; glr = g; glvl = g * vv;
        s_v[tid] = 0.f;
    }
    __syncthreads();

    float* hout; int st_t, st_b;
    if (layer == 0) { hout = g_h0; st_t = Bn * Hn; st_b = Hn;      }
    else            { hout = g_h1; st_t = Hn;      st_b = Tn * Hn; }

    for (int t = 0; t < Tn; t++) {
        float nsr = 0.f, dsr = 0.f;
        if (tid < Hn) {
            int off = (t * Bn + b) * Hn + tid;
            nsr = g_ns[off]; dsr = g_ds[off];
        }
        for (int u = 0; u < UNF; u++) {
            float4 accn = make_float4(0,0,0,0), accd = make_float4(0,0,0,0);
#pragma unroll
            for (int ii = 0; ii < 8; ii++) {
                int i = w * 8 + ii;
                float vi  = s_v[i];                                  // broadcast
                float4 A  = ((const float4*)(s_a + i * Hn))[lane];
                float4 Bv = ((const float4*)(s_b + i * Hn))[lane];
                float4 W  = ((const float4*)(s_w + i * Hn))[lane];
                float th, tv;
                th = tanh_fast(fmaf(vi, A.x, Bv.x)); tv = fmaf(W.x, th, W.x); accn.x += tv; accd.x += fabsf(tv);
                th = tanh_fast(fmaf(vi, A.y, Bv.y)); tv = fmaf(W.y, th, W.y); accn.y += tv; accd.y += fabsf(tv);
                th = tanh_fast(fmaf(vi, A.z, Bv.z)); tv = fmaf(W.z, th, W.z); accn.z += tv; accd.z += fabsf(tv);
                th = tanh_fast(fmaf(vi, A.w, Bv.w)); tv = fmaf(W.w, th, W.w); accn.w += tv; accd.w += fabsf(tv);
            }
            ((float4*)(s_pn + w * Hn))[lane] = accn;
            ((float4*)(s_pd + w * Hn))[lane] = accd;
            __syncthreads();
            if (tid < Hn) {
                float n = nsr, d = dsr;
#pragma unroll
                for (int c = 0; c < 16; c++) { n += s_pn[c * Hn + tid]; d += s_pd[c * Hn + tid]; }
                float vj = s_v[tid];
                float vn = __fdividef(fmaf(cmt, vj, glvl) + n, cmt + glr + d + EPSV);
                s_v[tid] = vn;
            }
            __syncthreads();
        }
        if (tid < Hn)
            hout[(size_t)t * st_t + (size_t)b * st_b + tid] = s_v[tid];
    }
}

// ---------------- dual linear heads ----------------
// C[64, 1024] = h1[64, 16384] @ [mu_w; ls_w]^T, exp() on the ls half.
// 128 blocks x 8 output columns, 256 threads = (64 batches x 4 col-pairs).
__global__ void __launch_bounds__(256) head_kernel(
    const float* __restrict__ mu_w, const float* __restrict__ mu_b,
    const float* __restrict__ ls_w, const float* __restrict__ ls_b,
    float* __restrict__ out)
{
    __shared__ float  sh[64][129];   // padded: (b + k) % 32 distinct -> conflict-free
    __shared__ float4 swt[8][32];
    const int tid = threadIdx.x;
    const int bb  = tid & 63;
    const int ng  = tid >> 6;        // 0..3 -> column pair
    const int n0  = blockIdx.x * 8;
    const bool is_ls = (n0 >= LATn);
    const float* wbase = is_ls ? (ls_w + (size_t)(n0 - LATn) * (Tn * Hn))
                               : (mu_w + (size_t)n0 * (Tn * Hn));
    float acc0 = 0.f, acc1 = 0.f;

    for (int k0 = 0; k0 < Tn * Hn; k0 += 128) {
        __syncthreads();
        for (int q = tid; q < 2048; q += 256) {           // h tile 64x128
            int r = q >> 5, kq = q & 31;
            float4 v = *(const float4*)(g_h1 + (size_t)r * (Tn * Hn) + k0 + kq * 4);
            sh[r][kq*4+0] = v.x; sh[r][kq*4+1] = v.y; sh[r][kq*4+2] = v.z; sh[r][kq*4+3] = v.w;
        }
        {                                                  // weight tile 8x128
            int r = tid >> 5, kq = tid & 31;
            swt[r][kq] = *(const float4*)(wbase + (size_t)r * (Tn * Hn) + k0 + kq * 4);
        }
        __syncthreads();
        const int na = ng * 2, nb = ng * 2 + 1;
#pragma unroll 8
        for (int kq = 0; kq < 32; kq++) {
            float4 w0 = swt[na][kq];
            float4 w1 = swt[nb][kq];
            float h0v = sh[bb][kq*4+0], h1v = sh[bb][kq*4+1];
            float h2v = sh[bb][kq*4+2], h3v = sh[bb][kq*4+3];
            acc0 = fmaf(h0v, w0.x, fmaf(h1v, w0.y, fmaf(h2v, w0.z, fmaf(h3v, w0.w, acc0))));
            acc1 = fmaf(h0v, w1.x, fmaf(h1v, w1.y, fmaf(h2v, w1.z, fmaf(h3v, w1.w, acc1))));
        }
    }
    int na_g = n0 + ng * 2;
    float o0, o1;
    if (!is_ls) { o0 = acc0 + mu_b[na_g];              o1 = acc1 + mu_b[na_g + 1]; }
    else        { o0 = expf(acc0 + ls_b[na_g - LATn]); o1 = expf(acc1 + ls_b[na_g - LATn + 1]); }
    int outcol = is_ls ? (na_g - LATn) : na_g;
    float* ob = out + (is_ls ? (size_t)Bn * LATn : 0);
    ob[(size_t)bb * LATn + outcol]     = o0;
    ob[(size_t)bb * LATn + outcol + 1] = o1;
}

// ---------------- launch ----------------
extern "C" void kernel_launch(void* const* d_in, const int* in_sizes, int n_in,
                              void* d_out, int out_size)
{
    const float* x      = (const float*)d_in[0];
    const float* gleak  = (const float*)d_in[1];
    const float* vleak  = (const float*)d_in[2];
    const float* cm     = (const float*)d_in[3];
    const float* sigma  = (const float*)d_in[4];
    const float* mu_syn = (const float*)d_in[5];
    const float* w      = (const float*)d_in[6];
    const float* erev   = (const float*)d_in[7];
    const float* s_sig  = (const float*)d_in[8];
    const float* s_mu   = (const float*)d_in[9];
    const float* s_w    = (const float*)d_in[10];
    const float* s_er   = (const float*)d_in[11];
    const float* mu_w   = (const float*)d_in[12];
    const float* mu_b   = (const float*)d_in[13];
    const float* ls_w   = (const float*)d_in[14];
    const float* ls_b   = (const float*)d_in[15];
    float* out = (float*)d_out;

    cudaFuncSetAttribute(scan_kernel, cudaFuncAttributeMaxDynamicSharedMemorySize, SCAN_SMEM_BYTES);

    prep_kernel<<<(Ln * Hn * Hn + 511) / 512, 512>>>(sigma, mu_syn, w, erev, s_sig, s_mu, s_w, s_er);

    dim3 sgrid(Tn / 4, Bn);
    sensory_kernel<<<sgrid, 256>>>(0, x);
    scan_kernel<<<Bn, 512, SCAN_SMEM_BYTES>>>(0, gleak, vleak, cm);
    sensory_kernel<<<sgrid, 256>>>(1, x);
    scan_kernel<<<Bn, 512, SCAN_SMEM_BYTES>>>(1, gleak, vleak, cm);
    head_kernel<<<(2 * LATn) / 8, 256>>>(mu_w, mu_b, ls_w, ls_b, out);
}

// round 4
// speedup vs baseline: 1.3413x; 1.3413x over previous
#include <cuda_runtime.h>
#include <cuda_bf16.h>
#include <cstdint>

#define Hn   128
#define Bn   64
#define Tn   128
#define Ln   2
#define LATn 512
#define UNF  6
#define EPSV 1e-8f

// ---------------- static device scratch ----------------
// transformed params: [layer][{rec_a, rec_b, rec_hwe, sen_a, sen_b, sen_hwe}][H*H]
__device__ float g_par[Ln][6][Hn * Hn];
__device__ float g_cn[Ln][Hn];         // column sums of rec_hwe
__device__ float g_cd[Ln][Hn];         // column sums of |rec_hwe|
__device__ float g_ns[Tn * Bn * Hn];   // sensory numerator  [T,B,H]
__device__ float g_ds[Tn * Bn * Hn];   // sensory denominator [T,B,H]
__device__ float g_h0[Tn * Bn * Hn];   // layer-0 hidden seq [T,B,H]
__device__ float g_h1[Bn * Tn * Hn];   // layer-1 hidden, flat [B, T*H]

__device__ __forceinline__ float tanh_fast(float x) {
    float y;
    asm("tanh.approx.f32 %0, %1;" : "=f"(y) : "f"(x));
    return y;
}

// ---------------- param transform ----------------
// rec_a = 0.5*sigma ; rec_b = -0.5*mu*sigma ; rec_hwe = 0.5*w*erev  (w>0, |erev|=1)
__global__ void prep_kernel(const float* __restrict__ sg,  const float* __restrict__ mu,
                            const float* __restrict__ w,   const float* __restrict__ er,
                            const float* __restrict__ ssg, const float* __restrict__ smu,
                            const float* __restrict__ sw,  const float* __restrict__ ser)
{
    int idx = blockIdx.x * blockDim.x + threadIdx.x;
    if (idx >= Ln * Hn * Hn) return;
    int l = idx >> 14;
    int k = idx & (Hn * Hn - 1);
    float a = sg[idx], m = mu[idx];
    g_par[l][0][k] = 0.5f * a;
    g_par[l][1][k] = -0.5f * m * a;
    g_par[l][2][k] = 0.5f * w[idx] * er[idx];
    float sa = ssg[idx], sm2 = smu[idx];
    g_par[l][3][k] = 0.5f * sa;
    g_par[l][4][k] = -0.5f * sm2 * sa;
    g_par[l][5][k] = 0.5f * sw[idx] * ser[idx];
}

// column sums over i for the recurrent weights (per output j)
__global__ void csum_kernel()
{
    int l = blockIdx.x;
    int j = threadIdx.x;
    float n = 0.f, d = 0.f;
    for (int i = 0; i < Hn; i++) {
        float h = g_par[l][2][i * Hn + j];
        n += h;
        d += fabsf(h);
    }
    g_cn[l][j] = n;
    g_cd[l][j] = d;
}

// ---------------- sensory precompute ----------------
__global__ void __launch_bounds__(256) sensory_kernel(int layer, const float* __restrict__ x)
{
    __shared__ float su[4][Hn];
    __shared__ float pn[4][8][Hn];
    __shared__ float pd[4][8][Hn];

    const int tg   = blockIdx.x;
    const int b    = blockIdx.y;
    const int t0   = tg * 4;
    const int tid  = threadIdx.x;
    const int w    = tid >> 5;
    const int lane = tid & 31;

    const float* ub; int ust, usb;
    if (layer == 0) { ub = x;    ust = Hn;      usb = Tn * Hn; }
    else            { ub = g_h0; ust = Bn * Hn; usb = Hn;      }

    for (int k = tid; k < 4 * Hn; k += 256) {
        int tt = k >> 7, i = k & 127;
        su[tt][i] = ub[(size_t)b * usb + (size_t)(t0 + tt) * ust + i];
    }
    __syncthreads();

    const float4* pa = (const float4*)g_par[layer][3];
    const float4* pb = (const float4*)g_par[layer][4];
    const float4* pw = (const float4*)g_par[layer][5];

    float4 an[4], ad[4];
#pragma unroll
    for (int tt = 0; tt < 4; tt++) { an[tt] = make_float4(0,0,0,0); ad[tt] = make_float4(0,0,0,0); }

#pragma unroll 2
    for (int ii = 0; ii < 16; ii++) {
        int i = w * 16 + ii;
        float4 A  = pa[i * 32 + lane];
        float4 Bv = pb[i * 32 + lane];
        float4 W  = pw[i * 32 + lane];
#pragma unroll
        for (int tt = 0; tt < 4; tt++) {
            float vi = su[tt][i];
            float th, tv;
            th = tanh_fast(fmaf(vi, A.x, Bv.x)); tv = fmaf(W.x, th, W.x); an[tt].x += tv; ad[tt].x += fabsf(tv);
            th = tanh_fast(fmaf(vi, A.y, Bv.y)); tv = fmaf(W.y, th, W.y); an[tt].y += tv; ad[tt].y += fabsf(tv);
            th = tanh_fast(fmaf(vi, A.z, Bv.z)); tv = fmaf(W.z, th, W.z); an[tt].z += tv; ad[tt].z += fabsf(tv);
            th = tanh_fast(fmaf(vi, A.w, Bv.w)); tv = fmaf(W.w, th, W.w); an[tt].w += tv; ad[tt].w += fabsf(tv);
        }
    }
#pragma unroll
    for (int tt = 0; tt < 4; tt++) {
        ((float4*)&pn[tt][w][0])[lane] = an[tt];
        ((float4*)&pd[tt][w][0])[lane] = ad[tt];
    }
    __syncthreads();

    for (int p = tid; p < 512; p += 256) {
        int tt = p >> 7, j = p & 127;
        float n = 0.f, d = 0.f;
#pragma unroll
        for (int c = 0; c < 8; c++) { n += pn[tt][c][j]; d += pd[tt][c][j]; }
        int off = ((t0 + tt) * Bn + b) * Hn + j;
        g_ns[off] = n;
        g_ds[off] = d;
    }
}

// ---------------- LTC scan: cluster-of-2, j-split, params in registers ----------------
// 128 CTAs, pairs share one batch. CTA rank r owns output neurons j in [64r, 64r+64).
// Per unfold: compute from s_v[cur], reduce, write new v to s_v[cur^1] locally AND in
// the peer CTA (plain DSMEM store), then one cluster barrier. Double buffering makes
// the cross-CTA store race-free regardless of CTA skew.
__global__ void __launch_bounds__(512, 1) __cluster_dims__(2, 1, 1)
scan_kernel(int layer, const float* __restrict__ gleak, const float* __restrict__ vleak,
            const float* __restrict__ cm)
{
    __shared__ float s_v[2][Hn];
    __shared__ float s_pn[16 * 64];
    __shared__ float s_pd[16 * 64];

    const int tid  = threadIdx.x;
    const int w    = tid >> 5;
    const int lane = tid & 31;
    const int b    = blockIdx.x >> 1;

    unsigned int rank;
    asm("mov.u32 %0, %%cluster_ctarank;" : "=r"(rank));
    const unsigned int peer = rank ^ 1u;

    if (tid < Hn) { s_v[0][tid] = 0.f; s_v[1][tid] = 0.f; }

    // ---- params into registers: thread (w, lane) covers i in [8w,8w+8), j = {64r+2lane, +1}
    float2 A2[8], B2[8], W2[8];
    {
        const int i0 = w * 8;
        const int jc = (int)rank * 64 + 2 * lane;
        const float* pa = g_par[layer][0];
        const float* pb = g_par[layer][1];
        const float* pw = g_par[layer][2];
#pragma unroll
        for (int ii = 0; ii < 8; ii++) {
            int off = (i0 + ii) * Hn + jc;
            A2[ii] = *(const float2*)(pa + off);
            B2[ii] = *(const float2*)(pb + off);
            W2[ii] = *(const float2*)(pw + off);
        }
    }

    // per-j constants + peer DSMEM address for the 64 reducer threads
    float cmt = 0.f, glr = 0.f, glvl = 0.f, cbn = 0.f, cbd = 0.f;
    unsigned int sv_remote_base = 0;   // peer's s_v[0][jg]
    if (tid < 64) {
        int jg = (int)rank * 64 + tid;
        float g  = gleak[layer * Hn + jg];
        float vv = vleak[layer * Hn + jg];
        float c  = cm[layer * Hn + jg];
        cmt = c * (float)UNF; glr = g; glvl = g * vv;
        cbn = g_cn[layer][jg]; cbd = g_cd[layer][jg];
        unsigned int la = (unsigned int)__cvta_generic_to_shared(&s_v[0][jg]);
        asm("mapa.shared::cluster.u32 %0, %1, %2;" : "=r"(sv_remote_base) : "r"(la), "r"(peer));
    }

    __syncthreads();
    asm volatile("barrier.cluster.arrive.aligned;" ::: "memory");
    asm volatile("barrier.cluster.wait.aligned;"   ::: "memory");

    float* hout; int st_t, st_b;
    if (layer == 0) { hout = g_h0; st_t = Bn * Hn; st_b = Hn;      }
    else            { hout = g_h1; st_t = Hn;      st_b = Tn * Hn; }

    int cur = 0;
    for (int t = 0; t < Tn; t++) {
        float nsr = 0.f, dsr = 0.f;
        if (tid < 64) {
            int off = (t * Bn + b) * Hn + (int)rank * 64 + tid;
            nsr = g_ns[off] + cbn;
            dsr = g_ds[off] + cbd;
        }
#pragma unroll 1
        for (int u = 0; u < UNF; u++) {
            const int nxt = cur ^ 1;
            float2 accn = make_float2(0.f, 0.f), accd = make_float2(0.f, 0.f);
#pragma unroll
            for (int ii = 0; ii < 8; ii++) {
                float vi  = s_v[cur][w * 8 + ii];
                float th0 = tanh_fast(fmaf(vi, A2[ii].x, B2[ii].x));
                float th1 = tanh_fast(fmaf(vi, A2[ii].y, B2[ii].y));
                accn.x = fmaf(W2[ii].x, th0, accn.x);
                accn.y = fmaf(W2[ii].y, th1, accn.y);
                accd.x = fmaf(fabsf(W2[ii].x), th0, accd.x);   // |hwe| via free |src| modifier
                accd.y = fmaf(fabsf(W2[ii].y), th1, accd.y);
            }
            *(float2*)&s_pn[w * 64 + 2 * lane] = accn;
            *(float2*)&s_pd[w * 64 + 2 * lane] = accd;
            __syncthreads();

            if (tid < 64) {
                float n = nsr, d = dsr;
#pragma unroll
                for (int c = 0; c < 16; c++) { n += s_pn[c * 64 + tid]; d += s_pd[c * 64 + tid]; }
                int jg = (int)rank * 64 + tid;
                float vj = s_v[cur][jg];
                float vnew = __fdividef(fmaf(cmt, vj, glvl) + n, cmt + glr + d + EPSV);
                s_v[nxt][jg] = vnew;
                // push to peer's s_v[nxt][jg] (disjoint range; visibility via cluster barrier)
                asm volatile("st.shared::cluster.b32 [%0], %1;"
                             :: "r"(sv_remote_base + 4u * (unsigned int)(nxt * Hn)),
                                "r"(__float_as_uint(vnew)) : "memory");
            }
            asm volatile("barrier.cluster.arrive.aligned;" ::: "memory");
            asm volatile("barrier.cluster.wait.aligned;"   ::: "memory");
            cur = nxt;
        }
        if (tid < 64) {
            int jg = (int)rank * 64 + tid;
            hout[(size_t)t * st_t + (size_t)b * st_b + jg] = s_v[cur][jg];
        }
    }
}

// ---------------- dual linear heads ----------------
__global__ void __launch_bounds__(256) head_kernel(
    const float* __restrict__ mu_w, const float* __restrict__ mu_b,
    const float* __restrict__ ls_w, const float* __restrict__ ls_b,
    float* __restrict__ out)
{
    __shared__ float  sh[64][129];
    __shared__ float4 swt[8][32];
    const int tid = threadIdx.x;
    const int bb  = tid & 63;
    const int ng  = tid >> 6;
    const int n0  = blockIdx.x * 8;
    const bool is_ls = (n0 >= LATn);
    const float* wbase = is_ls ? (ls_w + (size_t)(n0 - LATn) * (Tn * Hn))
                               : (mu_w + (size_t)n0 * (Tn * Hn));
    float acc0 = 0.f, acc1 = 0.f;

    for (int k0 = 0; k0 < Tn * Hn; k0 += 128) {
        __syncthreads();
        for (int q = tid; q < 2048; q += 256) {
            int r = q >> 5, kq = q & 31;
            float4 v = *(const float4*)(g_h1 + (size_t)r * (Tn * Hn) + k0 + kq * 4);
            sh[r][kq*4+0] = v.x; sh[r][kq*4+1] = v.y; sh[r][kq*4+2] = v.z; sh[r][kq*4+3] = v.w;
        }
        {
            int r = tid >> 5, kq = tid & 31;
            swt[r][kq] = *(const float4*)(wbase + (size_t)r * (Tn * Hn) + k0 + kq * 4);
        }
        __syncthreads();
        const int na = ng * 2, nb = ng * 2 + 1;
#pragma unroll 8
        for (int kq = 0; kq < 32; kq++) {
            float4 w0 = swt[na][kq];
            float4 w1 = swt[nb][kq];
            float h0v = sh[bb][kq*4+0], h1v = sh[bb][kq*4+1];
            float h2v = sh[bb][kq*4+2], h3v = sh[bb][kq*4+3];
            acc0 = fmaf(h0v, w0.x, fmaf(h1v, w0.y, fmaf(h2v, w0.z, fmaf(h3v, w0.w, acc0))));
            acc1 = fmaf(h0v, w1.x, fmaf(h1v, w1.y, fmaf(h2v, w1.z, fmaf(h3v, w1.w, acc1))));
        }
    }
    int na_g = n0 + ng * 2;
    float o0, o1;
    if (!is_ls) { o0 = acc0 + mu_b[na_g];              o1 = acc1 + mu_b[na_g + 1]; }
    else        { o0 = expf(acc0 + ls_b[na_g - LATn]); o1 = expf(acc1 + ls_b[na_g - LATn + 1]); }
    int outcol = is_ls ? (na_g - LATn) : na_g;
    float* ob = out + (is_ls ? (size_t)Bn * LATn : 0);
    ob[(size_t)bb * LATn + outcol]     = o0;
    ob[(size_t)bb * LATn + outcol + 1] = o1;
}

// ---------------- launch ----------------
extern "C" void kernel_launch(void* const* d_in, const int* in_sizes, int n_in,
                              void* d_out, int out_size)
{
    const float* x      = (const float*)d_in[0];
    const float* gleak  = (const float*)d_in[1];
    const float* vleak  = (const float*)d_in[2];
    const float* cm     = (const float*)d_in[3];
    const float* sigma  = (const float*)d_in[4];
    const float* mu_syn = (const float*)d_in[5];
    const float* w      = (const float*)d_in[6];
    const float* erev   = (const float*)d_in[7];
    const float* s_sig  = (const float*)d_in[8];
    const float* s_mu   = (const float*)d_in[9];
    const float* s_w    = (const float*)d_in[10];
    const float* s_er   = (const float*)d_in[11];
    const float* mu_w   = (const float*)d_in[12];
    const float* mu_b   = (const float*)d_in[13];
    const float* ls_w   = (const float*)d_in[14];
    const float* ls_b   = (const float*)d_in[15];
    float* out = (float*)d_out;

    prep_kernel<<<(Ln * Hn * Hn + 511) / 512, 512>>>(sigma, mu_syn, w, erev, s_sig, s_mu, s_w, s_er);
    csum_kernel<<<Ln, Hn>>>();

    dim3 sgrid(Tn / 4, Bn);
    sensory_kernel<<<sgrid, 256>>>(0, x);
    scan_kernel<<<2 * Bn, 512>>>(0, gleak, vleak, cm);
    sensory_kernel<<<sgrid, 256>>>(1, x);
    scan_kernel<<<2 * Bn, 512>>>(1, gleak, vleak, cm);
    head_kernel<<<(2 * LATn) / 8, 256>>>(mu_w, mu_b, ls_w, ls_b, out);
}

// round 5
// speedup vs baseline: 1.5439x; 1.1510x over previous
#include <cuda_runtime.h>
#include <cuda_bf16.h>
#include <cstdint>

#define Hn   128
#define Bn   64
#define Tn   128
#define Ln   2
#define LATn 512
#define UNF  6
#define EPSV 1e-8f
#define TOTAL (Tn * UNF)

// ---------------- static device scratch ----------------
// transformed params: [layer][{rec_a, rec_b, rec_hwe, sen_a, sen_b, sen_hwe}][H*H]
__device__ float g_par[Ln][6][Hn * Hn];
__device__ float g_cn[Ln][Hn];         // column sums of rec_hwe
__device__ float g_cd[Ln][Hn];         // column sums of |rec_hwe|
__device__ float g_ns[Tn * Bn * Hn];   // sensory numerator  [T,B,H]
__device__ float g_ds[Tn * Bn * Hn];   // sensory denominator [T,B,H]
__device__ float g_h0[Tn * Bn * Hn];   // layer-0 hidden seq [T,B,H]
__device__ float g_h1[Bn * Tn * Hn];   // layer-1 hidden, flat [B, T*H]

__device__ __forceinline__ float tanh_fast(float x) {
    float y;
    asm("tanh.approx.f32 %0, %1;" : "=f"(y) : "f"(x));
    return y;
}

// ---------------- param transform ----------------
__global__ void prep_kernel(const float* __restrict__ sg,  const float* __restrict__ mu,
                            const float* __restrict__ w,   const float* __restrict__ er,
                            const float* __restrict__ ssg, const float* __restrict__ smu,
                            const float* __restrict__ sw,  const float* __restrict__ ser)
{
    int idx = blockIdx.x * blockDim.x + threadIdx.x;
    if (idx >= Ln * Hn * Hn) return;
    int l = idx >> 14;
    int k = idx & (Hn * Hn - 1);
    float a = sg[idx], m = mu[idx];
    g_par[l][0][k] = 0.5f * a;
    g_par[l][1][k] = -0.5f * m * a;
    g_par[l][2][k] = 0.5f * w[idx] * er[idx];
    float sa = ssg[idx], sm2 = smu[idx];
    g_par[l][3][k] = 0.5f * sa;
    g_par[l][4][k] = -0.5f * sm2 * sa;
    g_par[l][5][k] = 0.5f * sw[idx] * ser[idx];
}

__global__ void csum_kernel()
{
    int l = blockIdx.x;
    int j = threadIdx.x;
    float n = 0.f, d = 0.f;
    for (int i = 0; i < Hn; i++) {
        float h = g_par[l][2][i * Hn + j];
        n += h;
        d += fabsf(h);
    }
    g_cn[l][j] = n;
    g_cd[l][j] = d;
}

// ---------------- sensory precompute ----------------
__global__ void __launch_bounds__(256) sensory_kernel(int layer, const float* __restrict__ x)
{
    __shared__ float su[4][Hn];
    __shared__ float pn[4][8][Hn];
    __shared__ float pd[4][8][Hn];

    const int tg   = blockIdx.x;
    const int b    = blockIdx.y;
    const int t0   = tg * 4;
    const int tid  = threadIdx.x;
    const int w    = tid >> 5;
    const int lane = tid & 31;

    const float* ub; int ust, usb;
    if (layer == 0) { ub = x;    ust = Hn;      usb = Tn * Hn; }
    else            { ub = g_h0; ust = Bn * Hn; usb = Hn;      }

    for (int k = tid; k < 4 * Hn; k += 256) {
        int tt = k >> 7, i = k & 127;
        su[tt][i] = ub[(size_t)b * usb + (size_t)(t0 + tt) * ust + i];
    }
    __syncthreads();

    const float4* pa = (const float4*)g_par[layer][3];
    const float4* pb = (const float4*)g_par[layer][4];
    const float4* pw = (const float4*)g_par[layer][5];

    float4 an[4], ad[4];
#pragma unroll
    for (int tt = 0; tt < 4; tt++) { an[tt] = make_float4(0,0,0,0); ad[tt] = make_float4(0,0,0,0); }

#pragma unroll 2
    for (int ii = 0; ii < 16; ii++) {
        int i = w * 16 + ii;
        float4 A  = pa[i * 32 + lane];
        float4 Bv = pb[i * 32 + lane];
        float4 W  = pw[i * 32 + lane];
#pragma unroll
        for (int tt = 0; tt < 4; tt++) {
            float vi = su[tt][i];
            float th, tv;
            th = tanh_fast(fmaf(vi, A.x, Bv.x)); tv = fmaf(W.x, th, W.x); an[tt].x += tv; ad[tt].x += fabsf(tv);
            th = tanh_fast(fmaf(vi, A.y, Bv.y)); tv = fmaf(W.y, th, W.y); an[tt].y += tv; ad[tt].y += fabsf(tv);
            th = tanh_fast(fmaf(vi, A.z, Bv.z)); tv = fmaf(W.z, th, W.z); an[tt].z += tv; ad[tt].z += fabsf(tv);
            th = tanh_fast(fmaf(vi, A.w, Bv.w)); tv = fmaf(W.w, th, W.w); an[tt].w += tv; ad[tt].w += fabsf(tv);
        }
    }
#pragma unroll
    for (int tt = 0; tt < 4; tt++) {
        ((float4*)&pn[tt][w][0])[lane] = an[tt];
        ((float4*)&pd[tt][w][0])[lane] = ad[tt];
    }
    __syncthreads();

    for (int p = tid; p < 512; p += 256) {
        int tt = p >> 7, j = p & 127;
        float n = 0.f, d = 0.f;
#pragma unroll
        for (int c = 0; c < 8; c++) { n += pn[tt][c][j]; d += pd[tt][c][j]; }
        int off = ((t0 + tt) * Bn + b) * Hn + j;
        g_ns[off] = n;
        g_ds[off] = d;
    }
}

// ---------------- LTC scan: cluster-of-2, warp-local reduce, mbar exchange ----------------
// 128 CTAs, pairs share one batch. CTA rank r owns j in [64r, 64r+64).
// Warp w owns 4 j's (jg = 64r + 4w + lane/8); 8 lanes per j, 16 i's per lane
// (8 own-half + 8 peer-half). Per unfold: phase A (own-half i), mbar wait for
// peer data, phase B (peer-half i), shfl-reduce over the 8-lane group, leader
// lane writes v locally + st.async to the peer. Double-buffered s_v.
__global__ void __launch_bounds__(512, 1) __cluster_dims__(2, 1, 1)
scan_kernel(int layer, const float* __restrict__ gleak, const float* __restrict__ vleak,
            const float* __restrict__ cm)
{
    __shared__ float s_v[2][Hn];
    __shared__ __align__(16) unsigned long long s_mbar[2];

    const int tid  = threadIdx.x;
    const int w    = tid >> 5;
    const int lane = tid & 31;
    const int s    = lane & 7;        // i-slice within j-group
    const int jj   = lane >> 3;       // which of the warp's 4 j's
    const int b    = blockIdx.x >> 1;

    unsigned int rank;
    asm("mov.u32 %0, %%cluster_ctarank;" : "=r"(rank));
    const unsigned int peer = rank ^ 1u;

    const int jg      = (int)rank * 64 + w * 4 + jj;
    const bool leader = (s == 0);
    const int i_own0  = (int)rank * 64 + s * 8;
    const int i_peer0 = (int)peer * 64 + s * 8;

    const unsigned int mbar_addr = (unsigned int)__cvta_generic_to_shared(&s_mbar[0]);
    if (tid == 0) {
        asm volatile("mbarrier.init.shared.b64 [%0], 1;" :: "r"(mbar_addr)      : "memory");
        asm volatile("mbarrier.init.shared.b64 [%0], 1;" :: "r"(mbar_addr + 8u) : "memory");
    }
    if (tid < Hn) { s_v[0][tid] = 0.f; s_v[1][tid] = 0.f; }

    // ---- params into registers: 16 (A,B,W) triples for fixed j (8 own-i, 8 peer-i)
    float A[16], B[16], W[16];
    {
        const float* pa = g_par[layer][0];
        const float* pb = g_par[layer][1];
        const float* pw = g_par[layer][2];
#pragma unroll
        for (int k = 0; k < 8; k++) {
            int off = (i_own0 + k) * Hn + jg;
            A[k] = pa[off]; B[k] = pb[off]; W[k] = pw[off];
        }
#pragma unroll
        for (int k = 0; k < 8; k++) {
            int off = (i_peer0 + k) * Hn + jg;
            A[8 + k] = pa[off]; B[8 + k] = pb[off]; W[8 + k] = pw[off];
        }
    }

    // per-j constants (same for all 8 lanes of a group; only leader uses them)
    float g   = gleak[layer * Hn + jg];
    float vv  = vleak[layer * Hn + jg];
    float c   = cm[layer * Hn + jg];
    const float cmt  = c * (float)UNF;
    const float glr  = g;
    const float glvl = g * vv;
    const float cbn  = g_cn[layer][jg];
    const float cbd  = g_cd[layer][jg];

    // remote addresses
    unsigned int sv_remote0, mb_remote;
    {
        unsigned int la = (unsigned int)__cvta_generic_to_shared(&s_v[0][jg]);
        asm("mapa.shared::cluster.u32 %0, %1, %2;" : "=r"(sv_remote0) : "r"(la), "r"(peer));
        asm("mapa.shared::cluster.u32 %0, %1, %2;" : "=r"(mb_remote)  : "r"(mbar_addr), "r"(peer));
    }

    __syncthreads();
    asm volatile("barrier.cluster.arrive.aligned;" ::: "memory");
    asm volatile("barrier.cluster.wait.aligned;"   ::: "memory");

    float* hout; int st_t, st_b;
    if (layer == 0) { hout = g_h0; st_t = Bn * Hn; st_b = Hn;      }
    else            { hout = g_h1; st_t = Hn;      st_b = Tn * Hn; }

#define STEP(vi, k) { float th = tanh_fast(fmaf((vi), A[k], B[k])); \
                      accn = fmaf(W[k], th, accn); accd = fmaf(fabsf(W[k]), th, accd); }

    float vj = 0.f;   // leader's own v[jg]
    int cnt = 0;
    for (int t = 0; t < Tn; t++) {
        float nsr = 0.f, dsr = 0.f;
        if (leader) {
            int off = (t * Bn + b) * Hn + jg;
            nsr = g_ns[off] + cbn;
            dsr = g_ds[off] + cbd;
        }
#pragma unroll 1
        for (int u = 0; u < UNF; u++) {
            const int curb = cnt & 1;
            const int nxtb = curb ^ 1;
            if (tid == 0 && cnt < TOTAL - 1) {
                asm volatile("mbarrier.arrive.expect_tx.shared.b64 _, [%0], 256;"
                             :: "r"(mbar_addr + 8u * (unsigned)curb) : "memory");
            }
            float accn = 0.f, accd = 0.f;
            // ---- phase A: own-half i (locally produced last unfold)
            {
                float4 va = *(const float4*)&s_v[curb][i_own0];
                float4 vb = *(const float4*)&s_v[curb][i_own0 + 4];
                STEP(va.x, 0) STEP(va.y, 1) STEP(va.z, 2) STEP(va.w, 3)
                STEP(vb.x, 4) STEP(vb.y, 5) STEP(vb.z, 6) STEP(vb.w, 7)
            }
            // ---- wait for peer-half data (sent by peer at unfold cnt-1)
            if (cnt > 0) {
                const unsigned int wslot = (unsigned)((cnt - 1) & 1);
                const unsigned int wpar  = (unsigned)(((cnt - 1) >> 1) & 1);
                asm volatile(
                    "{\n\t"
                    ".reg .pred P;\n\t"
                    "WAIT_%=: \n\t"
                    "mbarrier.try_wait.parity.acquire.cta.shared::cta.b64 P, [%0], %1, 0x989680;\n\t"
                    "@P bra.uni DONE_%=;\n\t"
                    "bra.uni WAIT_%=;\n\t"
                    "DONE_%=:\n\t"
                    "}" :: "r"(mbar_addr + 8u * wslot), "r"(wpar) : "memory");
            }
            // ---- phase B: peer-half i
            {
                float4 vc = *(const float4*)&s_v[curb][i_peer0];
                float4 vd = *(const float4*)&s_v[curb][i_peer0 + 4];
                STEP(vc.x,  8) STEP(vc.y,  9) STEP(vc.z, 10) STEP(vc.w, 11)
                STEP(vd.x, 12) STEP(vd.y, 13) STEP(vd.z, 14) STEP(vd.w, 15)
            }
            // ---- reduce across the 8-lane group
            accn += __shfl_xor_sync(0xffffffffu, accn, 1, 8);
            accd += __shfl_xor_sync(0xffffffffu, accd, 1, 8);
            accn += __shfl_xor_sync(0xffffffffu, accn, 2, 8);
            accd += __shfl_xor_sync(0xffffffffu, accd, 2, 8);
            accn += __shfl_xor_sync(0xffffffffu, accn, 4, 8);
            accd += __shfl_xor_sync(0xffffffffu, accd, 4, 8);
            if (leader) {
                float n = nsr + accn, d = dsr + accd;
                float vnew = __fdividef(fmaf(cmt, vj, glvl) + n, cmt + glr + d + EPSV);
                vj = vnew;
                s_v[nxtb][jg] = vnew;
                if (cnt < TOTAL - 1) {
                    asm volatile("st.async.shared::cluster.mbarrier::complete_tx::bytes.b32 [%0], %1, [%2];"
                                 :: "r"(sv_remote0 + 512u * (unsigned)nxtb),
                                    "r"(__float_as_uint(vnew)),
                                    "r"(mb_remote + 8u * (unsigned)curb) : "memory");
                }
            }
            __syncthreads();
            cnt++;
        }
        if (leader)
            hout[(size_t)t * st_t + (size_t)b * st_b + jg] = vj;
    }
#undef STEP
    asm volatile("barrier.cluster.arrive.aligned;" ::: "memory");
    asm volatile("barrier.cluster.wait.aligned;"   ::: "memory");
}

// ---------------- dual linear heads ----------------
__global__ void __launch_bounds__(256) head_kernel(
    const float* __restrict__ mu_w, const float* __restrict__ mu_b,
    const float* __restrict__ ls_w, const float* __restrict__ ls_b,
    float* __restrict__ out)
{
    __shared__ float  sh[64][129];
    __shared__ float4 swt[8][32];
    const int tid = threadIdx.x;
    const int bb  = tid & 63;
    const int ng  = tid >> 6;
    const int n0  = blockIdx.x * 8;
    const bool is_ls = (n0 >= LATn);
    const float* wbase = is_ls ? (ls_w + (size_t)(n0 - LATn) * (Tn * Hn))
                               : (mu_w + (size_t)n0 * (Tn * Hn));
    float acc0 = 0.f, acc1 = 0.f;

    for (int k0 = 0; k0 < Tn * Hn; k0 += 128) {
        __syncthreads();
        for (int q = tid; q < 2048; q += 256) {
            int r = q >> 5, kq = q & 31;
            float4 v = *(const float4*)(g_h1 + (size_t)r * (Tn * Hn) + k0 + kq * 4);
            sh[r][kq*4+0] = v.x; sh[r][kq*4+1] = v.y; sh[r][kq*4+2] = v.z; sh[r][kq*4+3] = v.w;
        }
        {
            int r = tid >> 5, kq = tid & 31;
            swt[r][kq] = *(const float4*)(wbase + (size_t)r * (Tn * Hn) + k0 + kq * 4);
        }
        __syncthreads();
        const int na = ng * 2, nb = ng * 2 + 1;
#pragma unroll 8
        for (int kq = 0; kq < 32; kq++) {
            float4 w0 = swt[na][kq];
            float4 w1 = swt[nb][kq];
            float h0v = sh[bb][kq*4+0], h1v = sh[bb][kq*4+1];
            float h2v = sh[bb][kq*4+2], h3v = sh[bb][kq*4+3];
            acc0 = fmaf(h0v, w0.x, fmaf(h1v, w0.y, fmaf(h2v, w0.z, fmaf(h3v, w0.w, acc0))));
            acc1 = fmaf(h0v, w1.x, fmaf(h1v, w1.y, fmaf(h2v, w1.z, fmaf(h3v, w1.w, acc1))));
        }
    }
    int na_g = n0 + ng * 2;
    float o0, o1;
    if (!is_ls) { o0 = acc0 + mu_b[na_g];              o1 = acc1 + mu_b[na_g + 1]; }
    else        { o0 = expf(acc0 + ls_b[na_g - LATn]); o1 = expf(acc1 + ls_b[na_g - LATn + 1]); }
    int outcol = is_ls ? (na_g - LATn) : na_g;
    float* ob = out + (is_ls ? (size_t)Bn * LATn : 0);
    ob[(size_t)bb * LATn + outcol]     = o0;
    ob[(size_t)bb * LATn + outcol + 1] = o1;
}

// ---------------- launch ----------------
extern "C" void kernel_launch(void* const* d_in, const int* in_sizes, int n_in,
                              void* d_out, int out_size)
{
    const float* x      = (const float*)d_in[0];
    const float* gleak  = (const float*)d_in[1];
    const float* vleak  = (const float*)d_in[2];
    const float* cm     = (const float*)d_in[3];
    const float* sigma  = (const float*)d_in[4];
    const float* mu_syn = (const float*)d_in[5];
    const float* w      = (const float*)d_in[6];
    const float* erev   = (const float*)d_in[7];
    const float* s_sig  = (const float*)d_in[8];
    const float* s_mu   = (const float*)d_in[9];
    const float* s_w    = (const float*)d_in[10];
    const float* s_er   = (const float*)d_in[11];
    const float* mu_w   = (const float*)d_in[12];
    const float* mu_b   = (const float*)d_in[13];
    const float* ls_w   = (const float*)d_in[14];
    const float* ls_b   = (const float*)d_in[15];
    float* out = (float*)d_out;

    prep_kernel<<<(Ln * Hn * Hn + 511) / 512, 512>>>(sigma, mu_syn, w, erev, s_sig, s_mu, s_w, s_er);
    csum_kernel<<<Ln, Hn>>>();

    dim3 sgrid(Tn / 4, Bn);
    sensory_kernel<<<sgrid, 256>>>(0, x);
    scan_kernel<<<2 * Bn, 512>>>(0, gleak, vleak, cm);
    sensory_kernel<<<sgrid, 256>>>(1, x);
    scan_kernel<<<2 * Bn, 512>>>(1, gleak, vleak, cm);
    head_kernel<<<(2 * LATn) / 8, 256>>>(mu_w, mu_b, ls_w, ls_b, out);
}

// round 6
// speedup vs baseline: 1.5971x; 1.0344x over previous
#include <cuda_runtime.h>
#include <cuda_bf16.h>
#include <cstdint>

#define Hn   128
#define Bn   64
#define Tn   128
#define Ln   2
#define LATn 512
#define UNF  6
#define EPSV 1e-8f
#define TOTAL (Tn * UNF)

// ---------------- static device scratch ----------------
// transformed params: [layer][{rec_a, rec_b, rec_hwe, sen_a, sen_b, sen_hwe}][H*H]
__device__ float g_par[Ln][6][Hn * Hn];
__device__ float g_cn[Ln][Hn];         // column sums of rec_hwe
__device__ float g_cd[Ln][Hn];         // column sums of |rec_hwe|
__device__ float g_ns[Tn * Bn * Hn];   // sensory numerator  [T,B,H]
__device__ float g_ds[Tn * Bn * Hn];   // sensory denominator [T,B,H]
__device__ float g_h0[Tn * Bn * Hn];   // layer-0 hidden seq [T,B,H]
__device__ float g_h1[Bn * Tn * Hn];   // layer-1 hidden, flat [B, T*H]

__device__ __forceinline__ float tanh_fast(float x) {
    float y;
    asm("tanh.approx.f32 %0, %1;" : "=f"(y) : "f"(x));
    return y;
}

// ---------------- param transform ----------------
__global__ void prep_kernel(const float* __restrict__ sg,  const float* __restrict__ mu,
                            const float* __restrict__ w,   const float* __restrict__ er,
                            const float* __restrict__ ssg, const float* __restrict__ smu,
                            const float* __restrict__ sw,  const float* __restrict__ ser)
{
    int idx = blockIdx.x * blockDim.x + threadIdx.x;
    if (idx >= Ln * Hn * Hn) return;
    int l = idx >> 14;
    int k = idx & (Hn * Hn - 1);
    float a = sg[idx], m = mu[idx];
    g_par[l][0][k] = 0.5f * a;
    g_par[l][1][k] = -0.5f * m * a;
    g_par[l][2][k] = 0.5f * w[idx] * er[idx];
    float sa = ssg[idx], sm2 = smu[idx];
    g_par[l][3][k] = 0.5f * sa;
    g_par[l][4][k] = -0.5f * sm2 * sa;
    g_par[l][5][k] = 0.5f * sw[idx] * ser[idx];
}

__global__ void csum_kernel()
{
    int l = blockIdx.x;
    int j = threadIdx.x;
    float n = 0.f, d = 0.f;
    for (int i = 0; i < Hn; i++) {
        float h = g_par[l][2][i * Hn + j];
        n += h;
        d += fabsf(h);
    }
    g_cn[l][j] = n;
    g_cd[l][j] = d;
}

// ---------------- sensory precompute ----------------
__global__ void __launch_bounds__(256) sensory_kernel(int layer, const float* __restrict__ x)
{
    __shared__ float su[4][Hn];
    __shared__ float pn[4][8][Hn];
    __shared__ float pd[4][8][Hn];

    const int tg   = blockIdx.x;
    const int b    = blockIdx.y;
    const int t0   = tg * 4;
    const int tid  = threadIdx.x;
    const int w    = tid >> 5;
    const int lane = tid & 31;

    const float* ub; int ust, usb;
    if (layer == 0) { ub = x;    ust = Hn;      usb = Tn * Hn; }
    else            { ub = g_h0; ust = Bn * Hn; usb = Hn;      }

    for (int k = tid; k < 4 * Hn; k += 256) {
        int tt = k >> 7, i = k & 127;
        su[tt][i] = ub[(size_t)b * usb + (size_t)(t0 + tt) * ust + i];
    }
    __syncthreads();

    const float4* pa = (const float4*)g_par[layer][3];
    const float4* pb = (const float4*)g_par[layer][4];
    const float4* pw = (const float4*)g_par[layer][5];

    float4 an[4], ad[4];
#pragma unroll
    for (int tt = 0; tt < 4; tt++) { an[tt] = make_float4(0,0,0,0); ad[tt] = make_float4(0,0,0,0); }

#pragma unroll 2
    for (int ii = 0; ii < 16; ii++) {
        int i = w * 16 + ii;
        float4 A  = pa[i * 32 + lane];
        float4 Bv = pb[i * 32 + lane];
        float4 W  = pw[i * 32 + lane];
#pragma unroll
        for (int tt = 0; tt < 4; tt++) {
            float vi = su[tt][i];
            float th, tv;
            th = tanh_fast(fmaf(vi, A.x, Bv.x)); tv = fmaf(W.x, th, W.x); an[tt].x += tv; ad[tt].x += fabsf(tv);
            th = tanh_fast(fmaf(vi, A.y, Bv.y)); tv = fmaf(W.y, th, W.y); an[tt].y += tv; ad[tt].y += fabsf(tv);
            th = tanh_fast(fmaf(vi, A.z, Bv.z)); tv = fmaf(W.z, th, W.z); an[tt].z += tv; ad[tt].z += fabsf(tv);
            th = tanh_fast(fmaf(vi, A.w, Bv.w)); tv = fmaf(W.w, th, W.w); an[tt].w += tv; ad[tt].w += fabsf(tv);
        }
    }
#pragma unroll
    for (int tt = 0; tt < 4; tt++) {
        ((float4*)&pn[tt][w][0])[lane] = an[tt];
        ((float4*)&pd[tt][w][0])[lane] = ad[tt];
    }
    __syncthreads();

    for (int p = tid; p < 512; p += 256) {
        int tt = p >> 7, j = p & 127;
        float n = 0.f, d = 0.f;
#pragma unroll
        for (int c = 0; c < 8; c++) { n += pn[tt][c][j]; d += pd[tt][c][j]; }
        int off = ((t0 + tt) * Bn + b) * Hn + j;
        g_ns[off] = n;
        g_ds[off] = d;
    }
}

// ---------------- LTC scan: cluster-of-4 quarter-split, 2 CTAs/SM ----------------
// 256 CTAs of 256 threads; cluster (4,1,1) spans one batch, rank r owns j in
// [32r, 32r+32). 2 independent CTAs co-reside per SM so sync/wait latency of one
// chain hides under the other's MUFU work. Warp w owns 4 j's (jg = 32r+4w+lane/8),
// 8 lanes per j (s = lane&7), 16 i's per lane (4 per quarter: i = 32q+4s+m).
// Per unfold: wait for peer data of previous unfold, 16 tanh+2FMA, 3-round
// width-8 shfl reduce, leader writes v locally + st.async to 3 peers (expect_tx
// = 96 floats = 384B on one mbar slot). Double-buffered s_v; same safety
// argument as the 2-CTA version (expect covers all leaders => all peer reads of
// the colliding buffer completed before any CTA can advance 2 unfolds).
__global__ void __launch_bounds__(256, 2) __cluster_dims__(4, 1, 1)
scan_kernel(int layer, const float* __restrict__ gleak, const float* __restrict__ vleak,
            const float* __restrict__ cm)
{
    __shared__ float s_v[2][Hn];
    __shared__ __align__(16) unsigned long long s_mbar[2];

    const int tid  = threadIdx.x;
    const int w    = tid >> 5;        // 0..7
    const int lane = tid & 31;
    const int s    = lane & 7;        // i-slice within j-group
    const int jj   = lane >> 3;       // which of the warp's 4 j's
    const int b    = blockIdx.x >> 2;

    unsigned int rank;
    asm("mov.u32 %0, %%cluster_ctarank;" : "=r"(rank));

    const int jg      = (int)rank * 32 + w * 4 + jj;
    const bool leader = (s == 0);

    const unsigned int mbar_addr = (unsigned int)__cvta_generic_to_shared(&s_mbar[0]);
    if (tid == 0) {
        asm volatile("mbarrier.init.shared.b64 [%0], 1;" :: "r"(mbar_addr)      : "memory");
        asm volatile("mbarrier.init.shared.b64 [%0], 1;" :: "r"(mbar_addr + 8u) : "memory");
    }
    if (tid < Hn) { s_v[0][tid] = 0.f; s_v[1][tid] = 0.f; }

    // ---- params into registers: k = 4q+m  ->  i = 32q + 4s + m
    float A[16], B[16], W[16];
    {
        const float* pa = g_par[layer][0];
        const float* pb = g_par[layer][1];
        const float* pw = g_par[layer][2];
#pragma unroll
        for (int q = 0; q < 4; q++)
#pragma unroll
            for (int m = 0; m < 4; m++) {
                int off = (32 * q + 4 * s + m) * Hn + jg;
                A[4*q+m] = pa[off]; B[4*q+m] = pb[off]; W[4*q+m] = pw[off];
            }
    }

    // per-j constants
    float g   = gleak[layer * Hn + jg];
    float vv  = vleak[layer * Hn + jg];
    float c   = cm[layer * Hn + jg];
    const float cmt  = c * (float)UNF;
    const float glr  = g;
    const float glvl = g * vv;
    const float cbn  = g_cn[layer][jg];
    const float cbd  = g_cd[layer][jg];

    // remote addresses for the 3 peers
    unsigned int sv_rem[3], mb_rem[3];
    {
        unsigned int la = (unsigned int)__cvta_generic_to_shared(&s_v[0][jg]);
        int p = 0;
#pragma unroll
        for (unsigned int r = 0; r < 4; r++) {
            if (r == rank) continue;
            asm("mapa.shared::cluster.u32 %0, %1, %2;" : "=r"(sv_rem[p]) : "r"(la), "r"(r));
            asm("mapa.shared::cluster.u32 %0, %1, %2;" : "=r"(mb_rem[p]) : "r"(mbar_addr), "r"(r));
            p++;
        }
    }

    __syncthreads();
    asm volatile("barrier.cluster.arrive.aligned;" ::: "memory");
    asm volatile("barrier.cluster.wait.aligned;"   ::: "memory");

    float* hout; int st_t, st_b;
    if (layer == 0) { hout = g_h0; st_t = Bn * Hn; st_b = Hn;      }
    else            { hout = g_h1; st_t = Hn;      st_b = Tn * Hn; }

#define STEP(vi, k) { float th = tanh_fast(fmaf((vi), A[k], B[k])); \
                      accn = fmaf(W[k], th, accn); accd = fmaf(fabsf(W[k]), th, accd); }

    float vj = 0.f;
    int cnt = 0;
    for (int t = 0; t < Tn; t++) {
        float nsr = 0.f, dsr = 0.f;
        if (leader) {
            int off = (t * Bn + b) * Hn + jg;
            nsr = g_ns[off] + cbn;
            dsr = g_ds[off] + cbd;
        }
#pragma unroll 1
        for (int u = 0; u < UNF; u++) {
            const int curb = cnt & 1;
            const int nxtb = curb ^ 1;
            if (tid == 0 && cnt < TOTAL - 1) {
                asm volatile("mbarrier.arrive.expect_tx.shared.b64 _, [%0], 384;"
                             :: "r"(mbar_addr + 8u * (unsigned)curb) : "memory");
            }
            // wait for the 3 peers' values of this buffer (sent at unfold cnt-1)
            if (cnt > 0) {
                const unsigned int wslot = (unsigned)((cnt - 1) & 1);
                const unsigned int wpar  = (unsigned)(((cnt - 1) >> 1) & 1);
                asm volatile(
                    "{\n\t"
                    ".reg .pred P;\n\t"
                    "WAIT_%=: \n\t"
                    "mbarrier.try_wait.parity.acquire.cta.shared::cta.b64 P, [%0], %1, 0x989680;\n\t"
                    "@P bra.uni DONE_%=;\n\t"
                    "bra.uni WAIT_%=;\n\t"
                    "DONE_%=:\n\t"
                    "}" :: "r"(mbar_addr + 8u * wslot), "r"(wpar) : "memory");
            }
            float accn = 0.f, accd = 0.f;
#pragma unroll
            for (int q = 0; q < 4; q++) {
                float4 vq = *(const float4*)&s_v[curb][32 * q + 4 * s];
                STEP(vq.x, 4*q+0) STEP(vq.y, 4*q+1) STEP(vq.z, 4*q+2) STEP(vq.w, 4*q+3)
            }
            // ---- reduce across the 8-lane group
            accn += __shfl_xor_sync(0xffffffffu, accn, 1, 8);
            accd += __shfl_xor_sync(0xffffffffu, accd, 1, 8);
            accn += __shfl_xor_sync(0xffffffffu, accn, 2, 8);
            accd += __shfl_xor_sync(0xffffffffu, accd, 2, 8);
            accn += __shfl_xor_sync(0xffffffffu, accn, 4, 8);
            accd += __shfl_xor_sync(0xffffffffu, accd, 4, 8);
            if (leader) {
                float n = nsr + accn, d = dsr + accd;
                float vnew = __fdividef(fmaf(cmt, vj, glvl) + n, cmt + glr + d + EPSV);
                vj = vnew;
                s_v[nxtb][jg] = vnew;
                if (cnt < TOTAL - 1) {
                    unsigned int vbits = __float_as_uint(vnew);
#pragma unroll
                    for (int p = 0; p < 3; p++) {
                        asm volatile("st.async.shared::cluster.mbarrier::complete_tx::bytes.b32 [%0], %1, [%2];"
                                     :: "r"(sv_rem[p] + 512u * (unsigned)nxtb),
                                        "r"(vbits),
                                        "r"(mb_rem[p] + 8u * (unsigned)curb) : "memory");
                    }
                }
            }
            __syncthreads();
            cnt++;
        }
        if (leader)
            hout[(size_t)t * st_t + (size_t)b * st_b + jg] = vj;
    }
#undef STEP
    asm volatile("barrier.cluster.arrive.aligned;" ::: "memory");
    asm volatile("barrier.cluster.wait.aligned;"   ::: "memory");
}

// ---------------- dual linear heads ----------------
__global__ void __launch_bounds__(256) head_kernel(
    const float* __restrict__ mu_w, const float* __restrict__ mu_b,
    const float* __restrict__ ls_w, const float* __restrict__ ls_b,
    float* __restrict__ out)
{
    __shared__ float  sh[64][129];
    __shared__ float4 swt[8][32];
    const int tid = threadIdx.x;
    const int bb  = tid & 63;
    const int ng  = tid >> 6;
    const int n0  = blockIdx.x * 8;
    const bool is_ls = (n0 >= LATn);
    const float* wbase = is_ls ? (ls_w + (size_t)(n0 - LATn) * (Tn * Hn))
                               : (mu_w + (size_t)n0 * (Tn * Hn));
    float acc0 = 0.f, acc1 = 0.f;

    for (int k0 = 0; k0 < Tn * Hn; k0 += 128) {
        __syncthreads();
        for (int q = tid; q < 2048; q += 256) {
            int r = q >> 5, kq = q & 31;
            float4 v = *(const float4*)(g_h1 + (size_t)r * (Tn * Hn) + k0 + kq * 4);
            sh[r][kq*4+0] = v.x; sh[r][kq*4+1] = v.y; sh[r][kq*4+2] = v.z; sh[r][kq*4+3] = v.w;
        }
        {
            int r = tid >> 5, kq = tid & 31;
            swt[r][kq] = *(const float4*)(wbase + (size_t)r * (Tn * Hn) + k0 + kq * 4);
        }
        __syncthreads();
        const int na = ng * 2, nb = ng * 2 + 1;
#pragma unroll 8
        for (int kq = 0; kq < 32; kq++) {
            float4 w0 = swt[na][kq];
            float4 w1 = swt[nb][kq];
            float h0v = sh[bb][kq*4+0], h1v = sh[bb][kq*4+1];
            float h2v = sh[bb][kq*4+2], h3v = sh[bb][kq*4+3];
            acc0 = fmaf(h0v, w0.x, fmaf(h1v, w0.y, fmaf(h2v, w0.z, fmaf(h3v, w0.w, acc0))));
            acc1 = fmaf(h0v, w1.x, fmaf(h1v, w1.y, fmaf(h2v, w1.z, fmaf(h3v, w1.w, acc1))));
        }
    }
    int na_g = n0 + ng * 2;
    float o0, o1;
    if (!is_ls) { o0 = acc0 + mu_b[na_g];              o1 = acc1 + mu_b[na_g + 1]; }
    else        { o0 = expf(acc0 + ls_b[na_g - LATn]); o1 = expf(acc1 + ls_b[na_g - LATn + 1]); }
    int outcol = is_ls ? (na_g - LATn) : na_g;
    float* ob = out + (is_ls ? (size_t)Bn * LATn : 0);
    ob[(size_t)bb * LATn + outcol]     = o0;
    ob[(size_t)bb * LATn + outcol + 1] = o1;
}

// ---------------- launch ----------------
extern "C" void kernel_launch(void* const* d_in, const int* in_sizes, int n_in,
                              void* d_out, int out_size)
{
    const float* x      = (const float*)d_in[0];
    const float* gleak  = (const float*)d_in[1];
    const float* vleak  = (const float*)d_in[2];
    const float* cm     = (const float*)d_in[3];
    const float* sigma  = (const float*)d_in[4];
    const float* mu_syn = (const float*)d_in[5];
    const float* w      = (const float*)d_in[6];
    const float* erev   = (const float*)d_in[7];
    const float* s_sig  = (const float*)d_in[8];
    const float* s_mu   = (const float*)d_in[9];
    const float* s_w    = (const float*)d_in[10];
    const float* s_er   = (const float*)d_in[11];
    const float* mu_w   = (const float*)d_in[12];
    const float* mu_b   = (const float*)d_in[13];
    const float* ls_w   = (const float*)d_in[14];
    const float* ls_b   = (const float*)d_in[15];
    float* out = (float*)d_out;

    prep_kernel<<<(Ln * Hn * Hn + 511) / 512, 512>>>(sigma, mu_syn, w, erev, s_sig, s_mu, s_w, s_er);
    csum_kernel<<<Ln, Hn>>>();

    dim3 sgrid(Tn / 4, Bn);
    sensory_kernel<<<sgrid, 256>>>(0, x);
    scan_kernel<<<4 * Bn, 256>>>(0, gleak, vleak, cm);
    sensory_kernel<<<sgrid, 256>>>(1, x);
    scan_kernel<<<4 * Bn, 256>>>(1, gleak, vleak, cm);
    head_kernel<<<(2 * LATn) / 8, 256>>>(mu_w, mu_b, ls_w, ls_b, out);
}